// round 15
// baseline (speedup 1.0000x reference)
#include <cuda_runtime.h>
#include <cuda_fp16.h>
#include <math.h>
#include <stdint.h>

// Problem constants
#define B 8
#define L 2500
#define D 512
#define Y 8921
#define LP 2560            // L padded (K of GEMM2)

// GEMM geometry: CTA tile 128(M) x 128(N), K-chunk 64, 8 warps (32x64 each),
// 2 CTAs per SM. Single-pass fp16. B frags triple-buffered, A frags double.
#define KC 64
#define A_OFF 0
#define B_OFF 16384
#define STAGE_BYTES 32768            // A(16K)+B(16K), each 128x64 fp16
#define NSTAGE 3
#define SMEM_BYTES (NSTAGE * STAGE_BYTES)   // 98304/CTA; 2 CTAs = 192KB/SM

// ---------------------------------------------------------------------------
// Device scratch
// ---------------------------------------------------------------------------
#define XOFFE  ((size_t)B * L * D)
#define XTOFFE ((size_t)B * D * LP)
#define UOFFE  ((size_t)Y * D)
#define AOFFE2 ((size_t)B * Y * LP)
#define SOFFE  ((size_t)B * Y * L)

__device__ __align__(16) __half g_x2[XOFFE];
__device__ __align__(16) __half g_xT2[XTOFFE];
__device__ __align__(16) __half g_U2[UOFFE];
__device__ __align__(16) __half g_a2[AOFFE2];
__device__ __align__(16) __half g_s16[SOFFE];    // fp16 scores (gemm1 out)
__device__ __align__(16) float g_ypart[(size_t)B * Y * 4];  // per-dblock dots
__device__ float g_bce[B * Y];

// ---------------------------------------------------------------------------
// PTX helpers (base sm_103-legal)
// ---------------------------------------------------------------------------
__device__ __forceinline__ uint32_t smem_u32(const void* p) {
    uint32_t a;
    asm("{ .reg .u64 t; cvta.to.shared.u64 t, %1; cvt.u32.u64 %0, t; }"
        : "=r"(a) : "l"(p));
    return a;
}
__device__ __forceinline__ void cpa16(uint32_t dst, const void* src, int szbytes) {
    asm volatile("cp.async.cg.shared.global [%0], [%1], 16, %2;"
                 :: "r"(dst), "l"(src), "r"(szbytes) : "memory");
}
__device__ __forceinline__ void cpa_commit() {
    asm volatile("cp.async.commit_group;" ::: "memory");
}
template <int N>
__device__ __forceinline__ void cpa_wait() {
    asm volatile("cp.async.wait_group %0;" :: "n"(N) : "memory");
}
__device__ __forceinline__ void ldsm4(uint32_t* r, uint32_t addr) {
    asm volatile("ldmatrix.sync.aligned.m8n8.x4.shared.b16 {%0,%1,%2,%3}, [%4];"
                 : "=r"(r[0]), "=r"(r[1]), "=r"(r[2]), "=r"(r[3]) : "r"(addr));
}
__device__ __forceinline__ void mma16816(float* c, const uint32_t* a,
                                         uint32_t b0, uint32_t b1) {
    asm volatile(
        "mma.sync.aligned.m16n8k16.row.col.f32.f16.f16.f32 "
        "{%0,%1,%2,%3}, {%4,%5,%6,%7}, {%8,%9}, {%0,%1,%2,%3};"
        : "+f"(c[0]), "+f"(c[1]), "+f"(c[2]), "+f"(c[3])
        : "r"(a[0]), "r"(a[1]), "r"(a[2]), "r"(a[3]), "r"(b0), "r"(b1));
}

// 128B-row XOR swizzle: row r, 16B-chunk c (0..7)
__device__ __forceinline__ uint32_t swz128(int r, int c) {
    return (uint32_t)(r * 128 + ((c ^ (r & 7)) << 4));
}

// ---------------------------------------------------------------------------
// Core GEMM (unchanged from R14): fp16 in, fp32 acc; optional fused fw-dot.
// ---------------------------------------------------------------------------
template <int CHUNKS, int SA, int SB, typename OutT, bool FUSE_DOT>
__device__ __forceinline__ void gemm_core(
    const __half* __restrict__ Asrc, int nA,
    const __half* __restrict__ Bsrc, int nB,
    OutT* __restrict__ Co, int sC, int nrow, int ncol,
    const float* __restrict__ fwp,
    float* __restrict__ ypart)
{
    extern __shared__ __align__(128) char smem[];
    const uint32_t sb = smem_u32(smem);
    const int tid = threadIdx.x;
    const int lane = tid & 31;
    const int wid = tid >> 5;
    const int warp_m = wid >> 1;
    const int warp_n = wid & 1;
    const int rowsel = lane & 15;
    const int colsel = (lane >> 4) & 1;

    const int rT = tid >> 3, cT = tid & 7;
    uint32_t so[4];
    int szA[4], szB[4];
#pragma unroll
    for (int it = 0; it < 4; it++) {
        int r = rT + it * 32;
        so[it] = swz128(r, cT);
        szA[it] = (r < nA) ? 16 : 0;
        szB[it] = (r < nB) ? 16 : 0;
    }
    const __half* pA = Asrc + (size_t)rT * SA + cT * 8;
    const __half* pB = Bsrc + (size_t)rT * SB + cT * 8;

    auto load_a = [&](uint32_t st) {
#pragma unroll
        for (int it = 0; it < 4; it++)
            cpa16(st + A_OFF + so[it], pA + (size_t)(it * 32) * SA, szA[it]);
        pA += KC;
    };
    auto load_b = [&](uint32_t st) {
#pragma unroll
        for (int it = 0; it < 4; it++)
            cpa16(st + B_OFF + so[it], pB + (size_t)(it * 32) * SB, szB[it]);
        pB += KC;
    };

    uint32_t aBase[2]; int aX[2];
#pragma unroll
    for (int im = 0; im < 2; im++) {
        int r = warp_m * 32 + im * 16 + rowsel;
        aBase[im] = (uint32_t)(A_OFF + r * 128); aX[im] = r & 7;
    }
    uint32_t bBase[4]; int bX[4];
#pragma unroll
    for (int jn = 0; jn < 4; jn++) {
        int r = warp_n * 64 + jn * 16 + rowsel;
        bBase[jn] = (uint32_t)(B_OFF + r * 128); bX[jn] = r & 7;
    }
#define OFF_A(kk, im) (aBase[im] + (uint32_t)((((kk) * 2 + colsel) ^ aX[im]) << 4))
#define OFF_B(kk, jn) (bBase[jn] + (uint32_t)((((kk) * 2 + colsel) ^ bX[jn]) << 4))

    float acc[2][8][4];
#pragma unroll
    for (int i = 0; i < 2; i++)
#pragma unroll
        for (int j = 0; j < 8; j++)
#pragma unroll
            for (int q = 0; q < 4; q++) acc[i][j][q] = 0.0f;

    load_a(sb); load_b(sb); cpa_commit();
    if (CHUNKS > 1) { load_a(sb + STAGE_BYTES); load_b(sb + STAGE_BYTES); cpa_commit(); }

    uint32_t aHd[2][2][4];
    uint32_t bHb[3][4];
    uint32_t stg = 0;

#pragma unroll 1
    for (int c = 0; c < CHUNKS; c++) {
        if (c + 1 < CHUNKS) cpa_wait<1>(); else cpa_wait<0>();
        __syncthreads();

        const uint32_t s = sb + stg;
        uint32_t pstg = stg + 2 * STAGE_BYTES;
        if (pstg >= NSTAGE * STAGE_BYTES) pstg -= NSTAGE * STAGE_BYTES;
        const uint32_t pf = sb + pstg;
        const bool do_pf = (c + 2 < CHUNKS);

        ldsm4(aHd[0][0], s + OFF_A(0, 0));
        ldsm4(aHd[0][1], s + OFF_A(0, 1));
        ldsm4(bHb[0], s + OFF_B(0, 0));
        ldsm4(bHb[1], s + OFF_B(0, 1));

#pragma unroll
        for (int ph = 0; ph < 16; ph++) {
            const int kk = ph >> 2, jn = ph & 3;
            const int p = ph % 3;
            if (ph + 2 < 16) {
                const int nph = ph + 2;
                ldsm4(bHb[nph % 3], s + OFF_B(nph >> 2, nph & 3));
            }
            const uint32_t (*aC)[4] = aHd[kk & 1];
            mma16816(acc[0][2 * jn],     aC[0], bHb[p][0], bHb[p][2]);
            mma16816(acc[0][2 * jn + 1], aC[0], bHb[p][1], bHb[p][3]);
            mma16816(acc[1][2 * jn],     aC[1], bHb[p][0], bHb[p][2]);
            mma16816(acc[1][2 * jn + 1], aC[1], bHb[p][1], bHb[p][3]);
            if (jn == 1 && kk < 3) {
                ldsm4(aHd[(kk + 1) & 1][0], s + OFF_A(kk + 1, 0));
                ldsm4(aHd[(kk + 1) & 1][1], s + OFF_A(kk + 1, 1));
            }
            if (ph == 1 && do_pf) load_a(pf);
            if (ph == 2 && do_pf) { load_b(pf); cpa_commit(); }
        }

        stg += STAGE_BYTES;
        if (stg >= NSTAGE * STAGE_BYTES) stg = 0;
    }

    const int g = lane >> 2;
    const int t2 = (lane & 3) * 2;
#pragma unroll
    for (int im = 0; im < 2; im++) {
        int r0 = warp_m * 32 + im * 16 + g;
#pragma unroll
        for (int j = 0; j < 8; j++) {
            int cc = warp_n * 64 + j * 8 + t2;
#pragma unroll
            for (int hv = 0; hv < 2; hv++) {
                int rr = r0 + hv * 8;
                if (rr >= nrow) continue;
                OutT* pr = Co + (size_t)rr * sC;
                float v0 = acc[im][j][hv * 2 + 0];
                float v1 = acc[im][j][hv * 2 + 1];
                if (cc + 1 < ncol) {
                    if constexpr (sizeof(OutT) == 2) {
                        *reinterpret_cast<__half2*>(pr + cc) =
                            __floats2half2_rn(v0, v1);
                    } else {
                        pr[cc] = v0; pr[cc + 1] = v1;
                    }
                } else if (cc < ncol) {
                    if constexpr (sizeof(OutT) == 2) pr[cc] = __float2half(v0);
                    else                             pr[cc] = v0;
                }
            }
        }
    }

    if constexpr (FUSE_DOT) {
        float part[4];
#pragma unroll
        for (int e = 0; e < 4; e++) part[e] = 0.0f;
#pragma unroll
        for (int im = 0; im < 2; im++) {
#pragma unroll
            for (int hv = 0; hv < 2; hv++) {
                int rr = warp_m * 32 + im * 16 + hv * 8 + g;
                if (rr >= nrow) continue;
                const float* fr = fwp + (size_t)rr * D;
                float sacc = 0.f;
#pragma unroll
                for (int j = 0; j < 8; j++) {
                    int cc = warp_n * 64 + j * 8 + t2;
                    float2 w = *reinterpret_cast<const float2*>(fr + cc);
                    sacc = fmaf(w.x, acc[im][j][hv * 2 + 0], sacc);
                    sacc = fmaf(w.y, acc[im][j][hv * 2 + 1], sacc);
                }
                part[im * 2 + hv] = sacc;
            }
        }
#pragma unroll
        for (int e = 0; e < 4; e++) {
            part[e] += __shfl_xor_sync(0xffffffffu, part[e], 1);
            part[e] += __shfl_xor_sync(0xffffffffu, part[e], 2);
        }
        float* sp = reinterpret_cast<float*>(smem);
        __syncthreads();
        if ((lane & 3) == 0) {
#pragma unroll
            for (int im = 0; im < 2; im++)
#pragma unroll
                for (int hv = 0; hv < 2; hv++) {
                    int rl = warp_m * 32 + im * 16 + hv * 8 + g;
                    sp[rl * 2 + warp_n] = part[im * 2 + hv];
                }
        }
        __syncthreads();
        if (tid < 128 && tid < nrow)
            ypart[(size_t)tid * 4] = sp[tid * 2] + sp[tid * 2 + 1];
    }
#undef OFF_A
#undef OFF_B
}

// ---------------------------------------------------------------------------
// Per-batch GEMM wrappers
// ---------------------------------------------------------------------------
__global__ __launch_bounds__(256, 2)
void gemm1_tc(int b) {
    const int m0 = blockIdx.y * 128;
    const int n0 = blockIdx.x * 128;
    int nA = min(Y - m0, 128);
    int nB = min(L - n0, 128);
    gemm_core<D / KC, D, D, __half, false>(
        g_U2 + (size_t)m0 * D, nA,
        g_x2 + ((size_t)b * L + n0) * D, nB,
        g_s16 + ((size_t)b * Y + m0) * L + n0, L, nA, nB,
        nullptr, nullptr);
}

__global__ __launch_bounds__(256, 2)
void gemm2_tc(float* __restrict__ mout, const float* __restrict__ fw, int b) {
    const int m0 = blockIdx.y * 128;
    const int n0 = blockIdx.x * 128;
    int nA = min(Y - m0, 128);
    gemm_core<LP / KC, LP, LP, float, true>(
        g_a2 + ((size_t)b * Y + m0) * LP, nA,
        g_xT2 + ((size_t)b * D + n0) * LP, 128,
        mout + ((size_t)b * Y + m0) * D + n0, D, nA, 128,
        fw + (size_t)m0 * D + n0,
        g_ypart + ((size_t)b * Y + m0) * 4 + (n0 >> 7));
}

// ---------------------------------------------------------------------------
// Converters
// ---------------------------------------------------------------------------
__global__ __launch_bounds__(256)
void split_u(const float* __restrict__ src) {
    size_t n = UOFFE;
    for (size_t i = (size_t)blockIdx.x * 256 + threadIdx.x; i < n; i += (size_t)gridDim.x * 256)
        g_U2[i] = __float2half(src[i]);
}

__global__ __launch_bounds__(256)
void fuse_x(const float* __restrict__ x) {
    __shared__ float t[32][33];
    const int b  = blockIdx.z;
    const int l0 = blockIdx.x * 32;
    const int d0 = blockIdx.y * 32;
    const float* xb = x + (size_t)b * L * D;
    const int tx = threadIdx.x & 31;
    const int ty = threadIdx.x >> 5;
#pragma unroll
    for (int i = ty; i < 32; i += 8) {
        int l = l0 + i;
        float v = (l < L) ? xb[(size_t)l * D + d0 + tx] : 0.0f;
        t[i][tx] = v;
        if (l < L)
            g_x2[((size_t)b * L + l) * D + d0 + tx] = __float2half(v);
    }
    __syncthreads();
#pragma unroll
    for (int i = ty; i < 32; i += 8) {
        int d = d0 + i;
        int l = l0 + tx;
        size_t o = ((size_t)b * D + d) * LP + l;
        g_xT2[o] = __float2half(t[tx][i]);
    }
}

// ---------------------------------------------------------------------------
// Softmax (per batch): read fp16 scores, write fp32 alpha + fp16 a2
// ---------------------------------------------------------------------------
__global__ __launch_bounds__(256)
void softmax_rows(float* __restrict__ alpha, int b) {
    const int row = b * Y + blockIdx.x;
    const __half2* p2 = reinterpret_cast<const __half2*>(g_s16 + (size_t)row * L);
    float* pout = alpha + (size_t)row * L;
    const int tid = threadIdx.x;
    const int N2 = L / 2;

    float2 vals[5];
    int cnt = 0;
    float mx = -INFINITY;
    for (int i = tid; i < N2; i += 256) {
        float2 v = __half22float2(p2[i]);
        vals[cnt++] = v;
        mx = fmaxf(mx, fmaxf(v.x, v.y));
    }
    __shared__ float red[256];
    red[tid] = mx; __syncthreads();
    for (int s = 128; s > 0; s >>= 1) {
        if (tid < s) red[tid] = fmaxf(red[tid], red[tid + s]);
        __syncthreads();
    }
    mx = red[0];
    __syncthreads();

    float sum = 0.f;
    for (int c = 0; c < cnt; c++) {
        vals[c].x = expf(vals[c].x - mx);
        vals[c].y = expf(vals[c].y - mx);
        sum += vals[c].x + vals[c].y;
    }
    red[tid] = sum; __syncthreads();
    for (int s = 128; s > 0; s >>= 1) {
        if (tid < s) red[tid] += red[tid + s];
        __syncthreads();
    }
    float inv = 1.0f / red[0];

    __half2* a2p = reinterpret_cast<__half2*>(g_a2 + (size_t)row * LP);
    cnt = 0;
    for (int i = tid; i < N2; i += 256) {
        float vx = vals[cnt].x * inv;
        float vy = vals[cnt].y * inv;
        cnt++;
        pout[2 * i]     = vx;
        pout[2 * i + 1] = vy;
        a2p[i] = __floats2half2_rn(vx, vy);
    }
    __half2 z = __floats2half2_rn(0.f, 0.f);
    for (int i = N2 + tid; i < LP / 2; i += 256)
        a2p[i] = z;
}

// ---------------------------------------------------------------------------
// Final + loss
// ---------------------------------------------------------------------------
__global__ __launch_bounds__(256)
void final2(const float* __restrict__ fb,
            const float* __restrict__ target,
            float* __restrict__ out_y) {
    int r = blockIdx.x * 256 + threadIdx.x;
    if (r >= B * Y) return;
    const float* pp = g_ypart + (size_t)r * 4;
    float yv = (pp[0] + pp[1]) + (pp[2] + pp[3]) + fb[r % Y];
    out_y[r] = yv;
    float t = target[r];
    g_bce[r] = fmaxf(yv, 0.f) - yv * t + log1pf(expf(-fabsf(yv)));
}

__global__ __launch_bounds__(256)
void loss_reduce(float* __restrict__ out_loss) {
    __shared__ double sh[256];
    double s = 0.0;
    for (int i = threadIdx.x; i < B * Y; i += 256) s += (double)g_bce[i];
    sh[threadIdx.x] = s;
    __syncthreads();
    for (int st = 128; st > 0; st >>= 1) {
        if (threadIdx.x < st) sh[threadIdx.x] += sh[threadIdx.x + st];
        __syncthreads();
    }
    if (threadIdx.x == 0) out_loss[0] = (float)(sh[0] / (double)(B * Y));
}

// ---------------------------------------------------------------------------
// Launch: per-batch pipeline across two side streams (fork/join via events).
// Output layout: [y (B*Y), loss (1), alpha (B*Y*L), m (B*Y*D)]
// ---------------------------------------------------------------------------
extern "C" void kernel_launch(void* const* d_in, const int* in_sizes, int n_in,
                              void* d_out, int out_size) {
    const float* x      = (const float*)d_in[0];
    const float* target = (const float*)d_in[1];
    // d_in[2] = text_inputs (unused)
    const float* Uw     = (const float*)d_in[3];
    const float* fw     = (const float*)d_in[4];
    const float* fb     = (const float*)d_in[5];

    float* out       = (float*)d_out;
    float* out_y     = out;
    float* out_loss  = out + (size_t)B * Y;
    float* out_alpha = out_loss + 1;
    float* out_m     = out_alpha + (size_t)B * Y * L;

    // Lazy one-time stream/event creation (first call is the uncaptured
    // correctness run; no device-memory allocation involved).
    static cudaStream_t sA = nullptr, sB = nullptr;
    static cudaEvent_t ev0, evg[B], evj;
    if (sA == nullptr) {
        cudaStreamCreateWithFlags(&sA, cudaStreamNonBlocking);
        cudaStreamCreateWithFlags(&sB, cudaStreamNonBlocking);
        cudaEventCreateWithFlags(&ev0, cudaEventDisableTiming);
        for (int b = 0; b < B; b++)
            cudaEventCreateWithFlags(&evg[b], cudaEventDisableTiming);
        cudaEventCreateWithFlags(&evj, cudaEventDisableTiming);
        cudaFuncSetAttribute(gemm1_tc, cudaFuncAttributeMaxDynamicSharedMemorySize, SMEM_BYTES);
        cudaFuncSetAttribute(gemm2_tc, cudaFuncAttributeMaxDynamicSharedMemorySize, SMEM_BYTES);
    }

    // Preprocessing on the origin (captured) stream
    split_u<<<2048, 256>>>(Uw);
    fuse_x<<<dim3(LP / 32, D / 32, B), 256>>>(x);
    cudaEventRecord(ev0, 0);

    // Stream A: gemm1 per batch
    cudaStreamWaitEvent(sA, ev0, 0);
    for (int b = 0; b < B; b++) {
        gemm1_tc<<<dim3((L + 127) / 128, (Y + 127) / 128), 256, SMEM_BYTES, sA>>>(b);
        cudaEventRecord(evg[b], sA);
    }

    // Stream B: softmax(b) -> gemm2(b), gated on gemm1(b)
    for (int b = 0; b < B; b++) {
        cudaStreamWaitEvent(sB, evg[b], 0);
        softmax_rows<<<Y, 256, 0, sB>>>(out_alpha, b);
        gemm2_tc<<<dim3(D / 128, (Y + 127) / 128), 256, SMEM_BYTES, sB>>>(out_m, fw, b);
    }

    final2<<<(B * Y + 255) / 256, 256, 0, sB>>>(fb, target, out_y);
    loss_reduce<<<1, 256, 0, sB>>>(out_loss);

    // Join back to the origin stream
    cudaEventRecord(evj, sB);
    cudaStreamWaitEvent(0, evj, 0);
}

// round 16
// speedup vs baseline: 1.0333x; 1.0333x over previous
#include <cuda_runtime.h>
#include <cuda_fp16.h>
#include <math.h>
#include <stdint.h>

// Problem constants
#define B 8
#define L 2500
#define D 512
#define Y 8921
#define LP 2560            // L padded (K of GEMM2)

// Pipeline slicing
#define NSPLIT 4
#define BPS (B / NSPLIT)   // 2 batches per slice

// GEMM geometry: CTA tile 128(M) x 128(N), K-chunk 64, 8 warps (32x64 each),
// 2 CTAs per SM. Single-pass fp16.
#define KC 64
#define A_OFF 0
#define B_OFF 16384
#define STAGE_BYTES 32768
#define NSTAGE 3
#define SMEM_BYTES (NSTAGE * STAGE_BYTES)   // 98304/CTA; 2 CTAs = 192KB/SM

// ---------------------------------------------------------------------------
// Device scratch
// ---------------------------------------------------------------------------
#define XOFFE  ((size_t)B * L * D)
#define XTOFFE ((size_t)B * D * LP)
#define UOFFE  ((size_t)Y * D)
#define AOFFE2 ((size_t)B * Y * LP)
#define SOFFE  ((size_t)B * Y * L)

__device__ __align__(16) __half g_x2[XOFFE];
__device__ __align__(16) __half g_xT2[XTOFFE];
__device__ __align__(16) __half g_U2[UOFFE];
__device__ __align__(16) __half g_a2[AOFFE2];
__device__ __align__(16) __half g_s16[SOFFE];
__device__ __align__(16) float g_ypart[(size_t)B * Y * 4];
__device__ float g_bce[B * Y];

// ---------------------------------------------------------------------------
// PTX helpers
// ---------------------------------------------------------------------------
__device__ __forceinline__ uint32_t smem_u32(const void* p) {
    uint32_t a;
    asm("{ .reg .u64 t; cvta.to.shared.u64 t, %1; cvt.u32.u64 %0, t; }"
        : "=r"(a) : "l"(p));
    return a;
}
__device__ __forceinline__ void cpa16(uint32_t dst, const void* src, int szbytes) {
    asm volatile("cp.async.cg.shared.global [%0], [%1], 16, %2;"
                 :: "r"(dst), "l"(src), "r"(szbytes) : "memory");
}
__device__ __forceinline__ void cpa_commit() {
    asm volatile("cp.async.commit_group;" ::: "memory");
}
template <int N>
__device__ __forceinline__ void cpa_wait() {
    asm volatile("cp.async.wait_group %0;" :: "n"(N) : "memory");
}
__device__ __forceinline__ void ldsm4(uint32_t* r, uint32_t addr) {
    asm volatile("ldmatrix.sync.aligned.m8n8.x4.shared.b16 {%0,%1,%2,%3}, [%4];"
                 : "=r"(r[0]), "=r"(r[1]), "=r"(r[2]), "=r"(r[3]) : "r"(addr));
}
__device__ __forceinline__ void mma16816(float* c, const uint32_t* a,
                                         uint32_t b0, uint32_t b1) {
    asm volatile(
        "mma.sync.aligned.m16n8k16.row.col.f32.f16.f16.f32 "
        "{%0,%1,%2,%3}, {%4,%5,%6,%7}, {%8,%9}, {%0,%1,%2,%3};"
        : "+f"(c[0]), "+f"(c[1]), "+f"(c[2]), "+f"(c[3])
        : "r"(a[0]), "r"(a[1]), "r"(a[2]), "r"(a[3]), "r"(b0), "r"(b1));
}

__device__ __forceinline__ uint32_t swz128(int r, int c) {
    return (uint32_t)(r * 128 + ((c ^ (r & 7)) << 4));
}

// ---------------------------------------------------------------------------
// Core GEMM (frozen since R13/R14)
// ---------------------------------------------------------------------------
template <int CHUNKS, int SA, int SB, typename OutT, bool FUSE_DOT>
__device__ __forceinline__ void gemm_core(
    const __half* __restrict__ Asrc, int nA,
    const __half* __restrict__ Bsrc, int nB,
    OutT* __restrict__ Co, int sC, int nrow, int ncol,
    const float* __restrict__ fwp,
    float* __restrict__ ypart)
{
    extern __shared__ __align__(128) char smem[];
    const uint32_t sb = smem_u32(smem);
    const int tid = threadIdx.x;
    const int lane = tid & 31;
    const int wid = tid >> 5;
    const int warp_m = wid >> 1;
    const int warp_n = wid & 1;
    const int rowsel = lane & 15;
    const int colsel = (lane >> 4) & 1;

    const int rT = tid >> 3, cT = tid & 7;
    uint32_t so[4];
    int szA[4], szB[4];
#pragma unroll
    for (int it = 0; it < 4; it++) {
        int r = rT + it * 32;
        so[it] = swz128(r, cT);
        szA[it] = (r < nA) ? 16 : 0;
        szB[it] = (r < nB) ? 16 : 0;
    }
    const __half* pA = Asrc + (size_t)rT * SA + cT * 8;
    const __half* pB = Bsrc + (size_t)rT * SB + cT * 8;

    auto load_a = [&](uint32_t st) {
#pragma unroll
        for (int it = 0; it < 4; it++)
            cpa16(st + A_OFF + so[it], pA + (size_t)(it * 32) * SA, szA[it]);
        pA += KC;
    };
    auto load_b = [&](uint32_t st) {
#pragma unroll
        for (int it = 0; it < 4; it++)
            cpa16(st + B_OFF + so[it], pB + (size_t)(it * 32) * SB, szB[it]);
        pB += KC;
    };

    uint32_t aBase[2]; int aX[2];
#pragma unroll
    for (int im = 0; im < 2; im++) {
        int r = warp_m * 32 + im * 16 + rowsel;
        aBase[im] = (uint32_t)(A_OFF + r * 128); aX[im] = r & 7;
    }
    uint32_t bBase[4]; int bX[4];
#pragma unroll
    for (int jn = 0; jn < 4; jn++) {
        int r = warp_n * 64 + jn * 16 + rowsel;
        bBase[jn] = (uint32_t)(B_OFF + r * 128); bX[jn] = r & 7;
    }
#define OFF_A(kk, im) (aBase[im] + (uint32_t)((((kk) * 2 + colsel) ^ aX[im]) << 4))
#define OFF_B(kk, jn) (bBase[jn] + (uint32_t)((((kk) * 2 + colsel) ^ bX[jn]) << 4))

    float acc[2][8][4];
#pragma unroll
    for (int i = 0; i < 2; i++)
#pragma unroll
        for (int j = 0; j < 8; j++)
#pragma unroll
            for (int q = 0; q < 4; q++) acc[i][j][q] = 0.0f;

    load_a(sb); load_b(sb); cpa_commit();
    if (CHUNKS > 1) { load_a(sb + STAGE_BYTES); load_b(sb + STAGE_BYTES); cpa_commit(); }

    uint32_t aHd[2][2][4];
    uint32_t bHb[3][4];
    uint32_t stg = 0;

#pragma unroll 1
    for (int c = 0; c < CHUNKS; c++) {
        if (c + 1 < CHUNKS) cpa_wait<1>(); else cpa_wait<0>();
        __syncthreads();

        const uint32_t s = sb + stg;
        uint32_t pstg = stg + 2 * STAGE_BYTES;
        if (pstg >= NSTAGE * STAGE_BYTES) pstg -= NSTAGE * STAGE_BYTES;
        const uint32_t pf = sb + pstg;
        const bool do_pf = (c + 2 < CHUNKS);

        ldsm4(aHd[0][0], s + OFF_A(0, 0));
        ldsm4(aHd[0][1], s + OFF_A(0, 1));
        ldsm4(bHb[0], s + OFF_B(0, 0));
        ldsm4(bHb[1], s + OFF_B(0, 1));

#pragma unroll
        for (int ph = 0; ph < 16; ph++) {
            const int kk = ph >> 2, jn = ph & 3;
            const int p = ph % 3;
            if (ph + 2 < 16) {
                const int nph = ph + 2;
                ldsm4(bHb[nph % 3], s + OFF_B(nph >> 2, nph & 3));
            }
            const uint32_t (*aC)[4] = aHd[kk & 1];
            mma16816(acc[0][2 * jn],     aC[0], bHb[p][0], bHb[p][2]);
            mma16816(acc[0][2 * jn + 1], aC[0], bHb[p][1], bHb[p][3]);
            mma16816(acc[1][2 * jn],     aC[1], bHb[p][0], bHb[p][2]);
            mma16816(acc[1][2 * jn + 1], aC[1], bHb[p][1], bHb[p][3]);
            if (jn == 1 && kk < 3) {
                ldsm4(aHd[(kk + 1) & 1][0], s + OFF_A(kk + 1, 0));
                ldsm4(aHd[(kk + 1) & 1][1], s + OFF_A(kk + 1, 1));
            }
            if (ph == 1 && do_pf) load_a(pf);
            if (ph == 2 && do_pf) { load_b(pf); cpa_commit(); }
        }

        stg += STAGE_BYTES;
        if (stg >= NSTAGE * STAGE_BYTES) stg = 0;
    }

    const int g = lane >> 2;
    const int t2 = (lane & 3) * 2;
#pragma unroll
    for (int im = 0; im < 2; im++) {
        int r0 = warp_m * 32 + im * 16 + g;
#pragma unroll
        for (int j = 0; j < 8; j++) {
            int cc = warp_n * 64 + j * 8 + t2;
#pragma unroll
            for (int hv = 0; hv < 2; hv++) {
                int rr = r0 + hv * 8;
                if (rr >= nrow) continue;
                OutT* pr = Co + (size_t)rr * sC;
                float v0 = acc[im][j][hv * 2 + 0];
                float v1 = acc[im][j][hv * 2 + 1];
                if (cc + 1 < ncol) {
                    if constexpr (sizeof(OutT) == 2) {
                        *reinterpret_cast<__half2*>(pr + cc) =
                            __floats2half2_rn(v0, v1);
                    } else {
                        pr[cc] = v0; pr[cc + 1] = v1;
                    }
                } else if (cc < ncol) {
                    if constexpr (sizeof(OutT) == 2) pr[cc] = __float2half(v0);
                    else                             pr[cc] = v0;
                }
            }
        }
    }

    if constexpr (FUSE_DOT) {
        float part[4];
#pragma unroll
        for (int e = 0; e < 4; e++) part[e] = 0.0f;
#pragma unroll
        for (int im = 0; im < 2; im++) {
#pragma unroll
            for (int hv = 0; hv < 2; hv++) {
                int rr = warp_m * 32 + im * 16 + hv * 8 + g;
                if (rr >= nrow) continue;
                const float* fr = fwp + (size_t)rr * D;
                float sacc = 0.f;
#pragma unroll
                for (int j = 0; j < 8; j++) {
                    int cc = warp_n * 64 + j * 8 + t2;
                    float2 w = *reinterpret_cast<const float2*>(fr + cc);
                    sacc = fmaf(w.x, acc[im][j][hv * 2 + 0], sacc);
                    sacc = fmaf(w.y, acc[im][j][hv * 2 + 1], sacc);
                }
                part[im * 2 + hv] = sacc;
            }
        }
#pragma unroll
        for (int e = 0; e < 4; e++) {
            part[e] += __shfl_xor_sync(0xffffffffu, part[e], 1);
            part[e] += __shfl_xor_sync(0xffffffffu, part[e], 2);
        }
        float* sp = reinterpret_cast<float*>(smem);
        __syncthreads();
        if ((lane & 3) == 0) {
#pragma unroll
            for (int im = 0; im < 2; im++)
#pragma unroll
                for (int hv = 0; hv < 2; hv++) {
                    int rl = warp_m * 32 + im * 16 + hv * 8 + g;
                    sp[rl * 2 + warp_n] = part[im * 2 + hv];
                }
        }
        __syncthreads();
        if (tid < 128 && tid < nrow)
            ypart[(size_t)tid * 4] = sp[tid * 2] + sp[tid * 2 + 1];
    }
#undef OFF_A
#undef OFF_B
}

// ---------------------------------------------------------------------------
// Slice GEMM wrappers (b = b0 + blockIdx.z)
// ---------------------------------------------------------------------------
__global__ __launch_bounds__(256, 2)
void gemm1_tc(int b0) {
    const int b  = b0 + blockIdx.z;
    const int m0 = blockIdx.y * 128;
    const int n0 = blockIdx.x * 128;
    int nA = min(Y - m0, 128);
    int nB = min(L - n0, 128);
    gemm_core<D / KC, D, D, __half, false>(
        g_U2 + (size_t)m0 * D, nA,
        g_x2 + ((size_t)b * L + n0) * D, nB,
        g_s16 + ((size_t)b * Y + m0) * L + n0, L, nA, nB,
        nullptr, nullptr);
}

__global__ __launch_bounds__(256, 2)
void gemm2_tc(float* __restrict__ mout, const float* __restrict__ fw, int b0) {
    const int b  = b0 + blockIdx.z;
    const int m0 = blockIdx.y * 128;
    const int n0 = blockIdx.x * 128;
    int nA = min(Y - m0, 128);
    gemm_core<LP / KC, LP, LP, float, true>(
        g_a2 + ((size_t)b * Y + m0) * LP, nA,
        g_xT2 + ((size_t)b * D + n0) * LP, 128,
        mout + ((size_t)b * Y + m0) * D + n0, D, nA, 128,
        fw + (size_t)m0 * D + n0,
        g_ypart + ((size_t)b * Y + m0) * 4 + (n0 >> 7));
}

// ---------------------------------------------------------------------------
// Converters
// ---------------------------------------------------------------------------
__global__ __launch_bounds__(256)
void split_u(const float* __restrict__ src) {
    size_t n = UOFFE;
    for (size_t i = (size_t)blockIdx.x * 256 + threadIdx.x; i < n; i += (size_t)gridDim.x * 256)
        g_U2[i] = __float2half(src[i]);
}

__global__ __launch_bounds__(256)
void fuse_x(const float* __restrict__ x) {
    __shared__ float t[32][33];
    const int b  = blockIdx.z;
    const int l0 = blockIdx.x * 32;
    const int d0 = blockIdx.y * 32;
    const float* xb = x + (size_t)b * L * D;
    const int tx = threadIdx.x & 31;
    const int ty = threadIdx.x >> 5;
#pragma unroll
    for (int i = ty; i < 32; i += 8) {
        int l = l0 + i;
        float v = (l < L) ? xb[(size_t)l * D + d0 + tx] : 0.0f;
        t[i][tx] = v;
        if (l < L)
            g_x2[((size_t)b * L + l) * D + d0 + tx] = __float2half(v);
    }
    __syncthreads();
#pragma unroll
    for (int i = ty; i < 32; i += 8) {
        int d = d0 + i;
        int l = l0 + tx;
        size_t o = ((size_t)b * D + d) * LP + l;
        g_xT2[o] = __float2half(t[tx][i]);
    }
}

// ---------------------------------------------------------------------------
// Softmax slice: rows [b0*Y, (b0+BPS)*Y)
// ---------------------------------------------------------------------------
__global__ __launch_bounds__(256)
void softmax_rows(float* __restrict__ alpha, int b0) {
    const int row = b0 * Y + blockIdx.x;
    const __half2* p2 = reinterpret_cast<const __half2*>(g_s16 + (size_t)row * L);
    float* pout = alpha + (size_t)row * L;
    const int tid = threadIdx.x;
    const int N2 = L / 2;

    float2 vals[5];
    int cnt = 0;
    float mx = -INFINITY;
    for (int i = tid; i < N2; i += 256) {
        float2 v = __half22float2(p2[i]);
        vals[cnt++] = v;
        mx = fmaxf(mx, fmaxf(v.x, v.y));
    }
    __shared__ float red[256];
    red[tid] = mx; __syncthreads();
    for (int s = 128; s > 0; s >>= 1) {
        if (tid < s) red[tid] = fmaxf(red[tid], red[tid + s]);
        __syncthreads();
    }
    mx = red[0];
    __syncthreads();

    float sum = 0.f;
    for (int c = 0; c < cnt; c++) {
        vals[c].x = expf(vals[c].x - mx);
        vals[c].y = expf(vals[c].y - mx);
        sum += vals[c].x + vals[c].y;
    }
    red[tid] = sum; __syncthreads();
    for (int s = 128; s > 0; s >>= 1) {
        if (tid < s) red[tid] += red[tid + s];
        __syncthreads();
    }
    float inv = 1.0f / red[0];

    __half2* a2p = reinterpret_cast<__half2*>(g_a2 + (size_t)row * LP);
    cnt = 0;
    for (int i = tid; i < N2; i += 256) {
        float vx = vals[cnt].x * inv;
        float vy = vals[cnt].y * inv;
        cnt++;
        pout[2 * i]     = vx;
        pout[2 * i + 1] = vy;
        a2p[i] = __floats2half2_rn(vx, vy);
    }
    __half2 z = __floats2half2_rn(0.f, 0.f);
    for (int i = N2 + tid; i < LP / 2; i += 256)
        a2p[i] = z;
}

// ---------------------------------------------------------------------------
// Final + loss
// ---------------------------------------------------------------------------
__global__ __launch_bounds__(256)
void final2(const float* __restrict__ fb,
            const float* __restrict__ target,
            float* __restrict__ out_y) {
    int r = blockIdx.x * 256 + threadIdx.x;
    if (r >= B * Y) return;
    const float* pp = g_ypart + (size_t)r * 4;
    float yv = (pp[0] + pp[1]) + (pp[2] + pp[3]) + fb[r % Y];
    out_y[r] = yv;
    float t = target[r];
    g_bce[r] = fmaxf(yv, 0.f) - yv * t + log1pf(expf(-fabsf(yv)));
}

__global__ __launch_bounds__(256)
void loss_reduce(float* __restrict__ out_loss) {
    __shared__ double sh[256];
    double s = 0.0;
    for (int i = threadIdx.x; i < B * Y; i += 256) s += (double)g_bce[i];
    sh[threadIdx.x] = s;
    __syncthreads();
    for (int st = 128; st > 0; st >>= 1) {
        if (threadIdx.x < st) sh[threadIdx.x] += sh[threadIdx.x + st];
        __syncthreads();
    }
    if (threadIdx.x == 0) out_loss[0] = (float)(sh[0] / (double)(B * Y));
}

// ---------------------------------------------------------------------------
// Launch: 4-slice pipeline, 3 streams (g1 on origin; softmax on C; g2 on B).
// ---------------------------------------------------------------------------
extern "C" void kernel_launch(void* const* d_in, const int* in_sizes, int n_in,
                              void* d_out, int out_size) {
    const float* x      = (const float*)d_in[0];
    const float* target = (const float*)d_in[1];
    // d_in[2] = text_inputs (unused)
    const float* Uw     = (const float*)d_in[3];
    const float* fw     = (const float*)d_in[4];
    const float* fb     = (const float*)d_in[5];

    float* out       = (float*)d_out;
    float* out_y     = out;
    float* out_loss  = out + (size_t)B * Y;
    float* out_alpha = out_loss + 1;
    float* out_m     = out_alpha + (size_t)B * Y * L;

    static cudaStream_t sC = nullptr, sB = nullptr;
    static cudaEvent_t evG1[NSPLIT], evSM[NSPLIT], evj;
    if (sC == nullptr) {
        cudaStreamCreateWithFlags(&sC, cudaStreamNonBlocking);
        cudaStreamCreateWithFlags(&sB, cudaStreamNonBlocking);
        for (int i = 0; i < NSPLIT; i++) {
            cudaEventCreateWithFlags(&evG1[i], cudaEventDisableTiming);
            cudaEventCreateWithFlags(&evSM[i], cudaEventDisableTiming);
        }
        cudaEventCreateWithFlags(&evj, cudaEventDisableTiming);
        cudaFuncSetAttribute(gemm1_tc, cudaFuncAttributeMaxDynamicSharedMemorySize, SMEM_BYTES);
        cudaFuncSetAttribute(gemm2_tc, cudaFuncAttributeMaxDynamicSharedMemorySize, SMEM_BYTES);
    }

    // Preprocessing + all gemm1 slices on the origin stream (tensor stays hot)
    split_u<<<2048, 256>>>(Uw);
    fuse_x<<<dim3(LP / 32, D / 32, B), 256>>>(x);
    for (int i = 0; i < NSPLIT; i++) {
        gemm1_tc<<<dim3((L + 127) / 128, (Y + 127) / 128, BPS), 256, SMEM_BYTES>>>(i * BPS);
        cudaEventRecord(evG1[i], 0);
    }

    // Stream C: softmax per slice, gated on its gemm1
    for (int i = 0; i < NSPLIT; i++) {
        cudaStreamWaitEvent(sC, evG1[i], 0);
        softmax_rows<<<BPS * Y, 256, 0, sC>>>(out_alpha, i * BPS);
        cudaEventRecord(evSM[i], sC);
    }

    // Stream B: gemm2 per slice, gated on its softmax
    for (int i = 0; i < NSPLIT; i++) {
        cudaStreamWaitEvent(sB, evSM[i], 0);
        gemm2_tc<<<dim3(D / 128, (Y + 127) / 128, BPS), 256, SMEM_BYTES, sB>>>(out_m, fw, i * BPS);
    }

    final2<<<(B * Y + 255) / 256, 256, 0, sB>>>(fb, target, out_y);
    loss_reduce<<<1, 256, 0, sB>>>(out_loss);

    cudaEventRecord(evj, sB);
    cudaStreamWaitEvent(0, evj, 0);
}

// round 17
// speedup vs baseline: 1.0343x; 1.0009x over previous
#include <cuda_runtime.h>
#include <cuda_fp16.h>
#include <math.h>
#include <stdint.h>

// Problem constants
#define B 8
#define L 2500
#define D 512
#define Y 8921
#define LP 2560            // L padded (K of GEMM2)

// Pipeline slicing
#define NSPLIT 4
#define BPS (B / NSPLIT)   // 2 batches per slice

// GEMM geometry: CTA tile 128(M) x 128(N), K-chunk 64, 8 warps (32x64 each),
// 2 CTAs per SM. Single-pass fp16.
#define KC 64
#define A_OFF 0
#define B_OFF 16384
#define STAGE_BYTES 32768
#define NSTAGE 3
#define SMEM_BYTES (NSTAGE * STAGE_BYTES)   // 98304/CTA; 2 CTAs = 192KB/SM

// ---------------------------------------------------------------------------
// Device scratch
// ---------------------------------------------------------------------------
#define XOFFE  ((size_t)B * L * D)
#define XTOFFE ((size_t)B * D * LP)
#define UOFFE  ((size_t)Y * D)
#define AOFFE2 ((size_t)B * Y * LP)
#define SOFFE  ((size_t)B * Y * L)

__device__ __align__(16) __half g_x2[XOFFE];
__device__ __align__(16) __half g_xT2[XTOFFE];
__device__ __align__(16) __half g_U2[UOFFE];
__device__ __align__(16) __half g_a2[AOFFE2];
__device__ __align__(16) __half g_s16[SOFFE];
__device__ __align__(16) float g_ypart[(size_t)B * Y * 4];
__device__ float g_bce[B * Y];

// ---------------------------------------------------------------------------
// PTX helpers
// ---------------------------------------------------------------------------
__device__ __forceinline__ uint32_t smem_u32(const void* p) {
    uint32_t a;
    asm("{ .reg .u64 t; cvta.to.shared.u64 t, %1; cvt.u32.u64 %0, t; }"
        : "=r"(a) : "l"(p));
    return a;
}
__device__ __forceinline__ void cpa16(uint32_t dst, const void* src, int szbytes) {
    asm volatile("cp.async.cg.shared.global [%0], [%1], 16, %2;"
                 :: "r"(dst), "l"(src), "r"(szbytes) : "memory");
}
__device__ __forceinline__ void cpa_commit() {
    asm volatile("cp.async.commit_group;" ::: "memory");
}
template <int N>
__device__ __forceinline__ void cpa_wait() {
    asm volatile("cp.async.wait_group %0;" :: "n"(N) : "memory");
}
__device__ __forceinline__ void ldsm4(uint32_t* r, uint32_t addr) {
    asm volatile("ldmatrix.sync.aligned.m8n8.x4.shared.b16 {%0,%1,%2,%3}, [%4];"
                 : "=r"(r[0]), "=r"(r[1]), "=r"(r[2]), "=r"(r[3]) : "r"(addr));
}
__device__ __forceinline__ void mma16816(float* c, const uint32_t* a,
                                         uint32_t b0, uint32_t b1) {
    asm volatile(
        "mma.sync.aligned.m16n8k16.row.col.f32.f16.f16.f32 "
        "{%0,%1,%2,%3}, {%4,%5,%6,%7}, {%8,%9}, {%0,%1,%2,%3};"
        : "+f"(c[0]), "+f"(c[1]), "+f"(c[2]), "+f"(c[3])
        : "r"(a[0]), "r"(a[1]), "r"(a[2]), "r"(a[3]), "r"(b0), "r"(b1));
}

__device__ __forceinline__ uint32_t swz128(int r, int c) {
    return (uint32_t)(r * 128 + ((c ^ (r & 7)) << 4));
}

// ---------------------------------------------------------------------------
// Core GEMM (frozen since R13/R14)
// ---------------------------------------------------------------------------
template <int CHUNKS, int SA, int SB, typename OutT, bool FUSE_DOT>
__device__ __forceinline__ void gemm_core(
    const __half* __restrict__ Asrc, int nA,
    const __half* __restrict__ Bsrc, int nB,
    OutT* __restrict__ Co, int sC, int nrow, int ncol,
    const float* __restrict__ fwp,
    float* __restrict__ ypart)
{
    extern __shared__ __align__(128) char smem[];
    const uint32_t sb = smem_u32(smem);
    const int tid = threadIdx.x;
    const int lane = tid & 31;
    const int wid = tid >> 5;
    const int warp_m = wid >> 1;
    const int warp_n = wid & 1;
    const int rowsel = lane & 15;
    const int colsel = (lane >> 4) & 1;

    const int rT = tid >> 3, cT = tid & 7;
    uint32_t so[4];
    int szA[4], szB[4];
#pragma unroll
    for (int it = 0; it < 4; it++) {
        int r = rT + it * 32;
        so[it] = swz128(r, cT);
        szA[it] = (r < nA) ? 16 : 0;
        szB[it] = (r < nB) ? 16 : 0;
    }
    const __half* pA = Asrc + (size_t)rT * SA + cT * 8;
    const __half* pB = Bsrc + (size_t)rT * SB + cT * 8;

    auto load_a = [&](uint32_t st) {
#pragma unroll
        for (int it = 0; it < 4; it++)
            cpa16(st + A_OFF + so[it], pA + (size_t)(it * 32) * SA, szA[it]);
        pA += KC;
    };
    auto load_b = [&](uint32_t st) {
#pragma unroll
        for (int it = 0; it < 4; it++)
            cpa16(st + B_OFF + so[it], pB + (size_t)(it * 32) * SB, szB[it]);
        pB += KC;
    };

    uint32_t aBase[2]; int aX[2];
#pragma unroll
    for (int im = 0; im < 2; im++) {
        int r = warp_m * 32 + im * 16 + rowsel;
        aBase[im] = (uint32_t)(A_OFF + r * 128); aX[im] = r & 7;
    }
    uint32_t bBase[4]; int bX[4];
#pragma unroll
    for (int jn = 0; jn < 4; jn++) {
        int r = warp_n * 64 + jn * 16 + rowsel;
        bBase[jn] = (uint32_t)(B_OFF + r * 128); bX[jn] = r & 7;
    }
#define OFF_A(kk, im) (aBase[im] + (uint32_t)((((kk) * 2 + colsel) ^ aX[im]) << 4))
#define OFF_B(kk, jn) (bBase[jn] + (uint32_t)((((kk) * 2 + colsel) ^ bX[jn]) << 4))

    float acc[2][8][4];
#pragma unroll
    for (int i = 0; i < 2; i++)
#pragma unroll
        for (int j = 0; j < 8; j++)
#pragma unroll
            for (int q = 0; q < 4; q++) acc[i][j][q] = 0.0f;

    load_a(sb); load_b(sb); cpa_commit();
    if (CHUNKS > 1) { load_a(sb + STAGE_BYTES); load_b(sb + STAGE_BYTES); cpa_commit(); }

    uint32_t aHd[2][2][4];
    uint32_t bHb[3][4];
    uint32_t stg = 0;

#pragma unroll 1
    for (int c = 0; c < CHUNKS; c++) {
        if (c + 1 < CHUNKS) cpa_wait<1>(); else cpa_wait<0>();
        __syncthreads();

        const uint32_t s = sb + stg;
        uint32_t pstg = stg + 2 * STAGE_BYTES;
        if (pstg >= NSTAGE * STAGE_BYTES) pstg -= NSTAGE * STAGE_BYTES;
        const uint32_t pf = sb + pstg;
        const bool do_pf = (c + 2 < CHUNKS);

        ldsm4(aHd[0][0], s + OFF_A(0, 0));
        ldsm4(aHd[0][1], s + OFF_A(0, 1));
        ldsm4(bHb[0], s + OFF_B(0, 0));
        ldsm4(bHb[1], s + OFF_B(0, 1));

#pragma unroll
        for (int ph = 0; ph < 16; ph++) {
            const int kk = ph >> 2, jn = ph & 3;
            const int p = ph % 3;
            if (ph + 2 < 16) {
                const int nph = ph + 2;
                ldsm4(bHb[nph % 3], s + OFF_B(nph >> 2, nph & 3));
            }
            const uint32_t (*aC)[4] = aHd[kk & 1];
            mma16816(acc[0][2 * jn],     aC[0], bHb[p][0], bHb[p][2]);
            mma16816(acc[0][2 * jn + 1], aC[0], bHb[p][1], bHb[p][3]);
            mma16816(acc[1][2 * jn],     aC[1], bHb[p][0], bHb[p][2]);
            mma16816(acc[1][2 * jn + 1], aC[1], bHb[p][1], bHb[p][3]);
            if (jn == 1 && kk < 3) {
                ldsm4(aHd[(kk + 1) & 1][0], s + OFF_A(kk + 1, 0));
                ldsm4(aHd[(kk + 1) & 1][1], s + OFF_A(kk + 1, 1));
            }
            if (ph == 1 && do_pf) load_a(pf);
            if (ph == 2 && do_pf) { load_b(pf); cpa_commit(); }
        }

        stg += STAGE_BYTES;
        if (stg >= NSTAGE * STAGE_BYTES) stg = 0;
    }

    const int g = lane >> 2;
    const int t2 = (lane & 3) * 2;
#pragma unroll
    for (int im = 0; im < 2; im++) {
        int r0 = warp_m * 32 + im * 16 + g;
#pragma unroll
        for (int j = 0; j < 8; j++) {
            int cc = warp_n * 64 + j * 8 + t2;
#pragma unroll
            for (int hv = 0; hv < 2; hv++) {
                int rr = r0 + hv * 8;
                if (rr >= nrow) continue;
                OutT* pr = Co + (size_t)rr * sC;
                float v0 = acc[im][j][hv * 2 + 0];
                float v1 = acc[im][j][hv * 2 + 1];
                if (cc + 1 < ncol) {
                    if constexpr (sizeof(OutT) == 2) {
                        *reinterpret_cast<__half2*>(pr + cc) =
                            __floats2half2_rn(v0, v1);
                    } else {
                        pr[cc] = v0; pr[cc + 1] = v1;
                    }
                } else if (cc < ncol) {
                    if constexpr (sizeof(OutT) == 2) pr[cc] = __float2half(v0);
                    else                             pr[cc] = v0;
                }
            }
        }
    }

    if constexpr (FUSE_DOT) {
        float part[4];
#pragma unroll
        for (int e = 0; e < 4; e++) part[e] = 0.0f;
#pragma unroll
        for (int im = 0; im < 2; im++) {
#pragma unroll
            for (int hv = 0; hv < 2; hv++) {
                int rr = warp_m * 32 + im * 16 + hv * 8 + g;
                if (rr >= nrow) continue;
                const float* fr = fwp + (size_t)rr * D;
                float sacc = 0.f;
#pragma unroll
                for (int j = 0; j < 8; j++) {
                    int cc = warp_n * 64 + j * 8 + t2;
                    float2 w = *reinterpret_cast<const float2*>(fr + cc);
                    sacc = fmaf(w.x, acc[im][j][hv * 2 + 0], sacc);
                    sacc = fmaf(w.y, acc[im][j][hv * 2 + 1], sacc);
                }
                part[im * 2 + hv] = sacc;
            }
        }
#pragma unroll
        for (int e = 0; e < 4; e++) {
            part[e] += __shfl_xor_sync(0xffffffffu, part[e], 1);
            part[e] += __shfl_xor_sync(0xffffffffu, part[e], 2);
        }
        float* sp = reinterpret_cast<float*>(smem);
        __syncthreads();
        if ((lane & 3) == 0) {
#pragma unroll
            for (int im = 0; im < 2; im++)
#pragma unroll
                for (int hv = 0; hv < 2; hv++) {
                    int rl = warp_m * 32 + im * 16 + hv * 8 + g;
                    sp[rl * 2 + warp_n] = part[im * 2 + hv];
                }
        }
        __syncthreads();
        if (tid < 128 && tid < nrow)
            ypart[(size_t)tid * 4] = sp[tid * 2] + sp[tid * 2 + 1];
    }
#undef OFF_A
#undef OFF_B
}

// ---------------------------------------------------------------------------
// Slice GEMM wrappers (b = b0 + blockIdx.z)
// ---------------------------------------------------------------------------
__global__ __launch_bounds__(256, 2)
void gemm1_tc(int b0) {
    const int b  = b0 + blockIdx.z;
    const int m0 = blockIdx.y * 128;
    const int n0 = blockIdx.x * 128;
    int nA = min(Y - m0, 128);
    int nB = min(L - n0, 128);
    gemm_core<D / KC, D, D, __half, false>(
        g_U2 + (size_t)m0 * D, nA,
        g_x2 + ((size_t)b * L + n0) * D, nB,
        g_s16 + ((size_t)b * Y + m0) * L + n0, L, nA, nB,
        nullptr, nullptr);
}

__global__ __launch_bounds__(256, 2)
void gemm2_tc(float* __restrict__ mout, const float* __restrict__ fw, int b0) {
    const int b  = b0 + blockIdx.z;
    const int m0 = blockIdx.y * 128;
    const int n0 = blockIdx.x * 128;
    int nA = min(Y - m0, 128);
    gemm_core<LP / KC, LP, LP, float, true>(
        g_a2 + ((size_t)b * Y + m0) * LP, nA,
        g_xT2 + ((size_t)b * D + n0) * LP, 128,
        mout + ((size_t)b * Y + m0) * D + n0, D, nA, 128,
        fw + (size_t)m0 * D + n0,
        g_ypart + ((size_t)b * Y + m0) * 4 + (n0 >> 7));
}

// ---------------------------------------------------------------------------
// Converters
// ---------------------------------------------------------------------------
__global__ __launch_bounds__(256)
void split_u(const float* __restrict__ src) {
    size_t n = UOFFE;
    for (size_t i = (size_t)blockIdx.x * 256 + threadIdx.x; i < n; i += (size_t)gridDim.x * 256)
        g_U2[i] = __float2half(src[i]);
}

__global__ __launch_bounds__(256)
void fuse_x(const float* __restrict__ x) {
    __shared__ float t[32][33];
    const int b  = blockIdx.z;
    const int l0 = blockIdx.x * 32;
    const int d0 = blockIdx.y * 32;
    const float* xb = x + (size_t)b * L * D;
    const int tx = threadIdx.x & 31;
    const int ty = threadIdx.x >> 5;
#pragma unroll
    for (int i = ty; i < 32; i += 8) {
        int l = l0 + i;
        float v = (l < L) ? xb[(size_t)l * D + d0 + tx] : 0.0f;
        t[i][tx] = v;
        if (l < L)
            g_x2[((size_t)b * L + l) * D + d0 + tx] = __float2half(v);
    }
    __syncthreads();
#pragma unroll
    for (int i = ty; i < 32; i += 8) {
        int d = d0 + i;
        int l = l0 + tx;
        size_t o = ((size_t)b * D + d) * LP + l;
        g_xT2[o] = __float2half(t[tx][i]);
    }
}

// ---------------------------------------------------------------------------
// Softmax slice: rows [b0*Y, (b0+BPS)*Y)
// ---------------------------------------------------------------------------
__global__ __launch_bounds__(256)
void softmax_rows(float* __restrict__ alpha, int b0) {
    const int row = b0 * Y + blockIdx.x;
    const __half2* p2 = reinterpret_cast<const __half2*>(g_s16 + (size_t)row * L);
    float* pout = alpha + (size_t)row * L;
    const int tid = threadIdx.x;
    const int N2 = L / 2;

    float2 vals[5];
    int cnt = 0;
    float mx = -INFINITY;
    for (int i = tid; i < N2; i += 256) {
        float2 v = __half22float2(p2[i]);
        vals[cnt++] = v;
        mx = fmaxf(mx, fmaxf(v.x, v.y));
    }
    __shared__ float red[256];
    red[tid] = mx; __syncthreads();
    for (int s = 128; s > 0; s >>= 1) {
        if (tid < s) red[tid] = fmaxf(red[tid], red[tid + s]);
        __syncthreads();
    }
    mx = red[0];
    __syncthreads();

    float sum = 0.f;
    for (int c = 0; c < cnt; c++) {
        vals[c].x = expf(vals[c].x - mx);
        vals[c].y = expf(vals[c].y - mx);
        sum += vals[c].x + vals[c].y;
    }
    red[tid] = sum; __syncthreads();
    for (int s = 128; s > 0; s >>= 1) {
        if (tid < s) red[tid] += red[tid + s];
        __syncthreads();
    }
    float inv = 1.0f / red[0];

    __half2* a2p = reinterpret_cast<__half2*>(g_a2 + (size_t)row * LP);
    cnt = 0;
    for (int i = tid; i < N2; i += 256) {
        float vx = vals[cnt].x * inv;
        float vy = vals[cnt].y * inv;
        cnt++;
        pout[2 * i]     = vx;
        pout[2 * i + 1] = vy;
        a2p[i] = __floats2half2_rn(vx, vy);
    }
    __half2 z = __floats2half2_rn(0.f, 0.f);
    for (int i = N2 + tid; i < LP / 2; i += 256)
        a2p[i] = z;
}

// ---------------------------------------------------------------------------
// Final + loss
// ---------------------------------------------------------------------------
__global__ __launch_bounds__(256)
void final2(const float* __restrict__ fb,
            const float* __restrict__ target,
            float* __restrict__ out_y) {
    int r = blockIdx.x * 256 + threadIdx.x;
    if (r >= B * Y) return;
    const float* pp = g_ypart + (size_t)r * 4;
    float yv = (pp[0] + pp[1]) + (pp[2] + pp[3]) + fb[r % Y];
    out_y[r] = yv;
    float t = target[r];
    g_bce[r] = fmaxf(yv, 0.f) - yv * t + log1pf(expf(-fabsf(yv)));
}

__global__ __launch_bounds__(256)
void loss_reduce(float* __restrict__ out_loss) {
    __shared__ double sh[256];
    double s = 0.0;
    for (int i = threadIdx.x; i < B * Y; i += 256) s += (double)g_bce[i];
    sh[threadIdx.x] = s;
    __syncthreads();
    for (int st = 128; st > 0; st >>= 1) {
        if (threadIdx.x < st) sh[threadIdx.x] += sh[threadIdx.x + st];
        __syncthreads();
    }
    if (threadIdx.x == 0) out_loss[0] = (float)(sh[0] / (double)(B * Y));
}

// ---------------------------------------------------------------------------
// Launch: 4-slice pipeline, 3 streams (g1 on origin; softmax on C; g2 on B).
// ---------------------------------------------------------------------------
extern "C" void kernel_launch(void* const* d_in, const int* in_sizes, int n_in,
                              void* d_out, int out_size) {
    const float* x      = (const float*)d_in[0];
    const float* target = (const float*)d_in[1];
    // d_in[2] = text_inputs (unused)
    const float* Uw     = (const float*)d_in[3];
    const float* fw     = (const float*)d_in[4];
    const float* fb     = (const float*)d_in[5];

    float* out       = (float*)d_out;
    float* out_y     = out;
    float* out_loss  = out + (size_t)B * Y;
    float* out_alpha = out_loss + 1;
    float* out_m     = out_alpha + (size_t)B * Y * L;

    static cudaStream_t sC = nullptr, sB = nullptr;
    static cudaEvent_t evG1[NSPLIT], evSM[NSPLIT], evj;
    if (sC == nullptr) {
        cudaStreamCreateWithFlags(&sC, cudaStreamNonBlocking);
        cudaStreamCreateWithFlags(&sB, cudaStreamNonBlocking);
        for (int i = 0; i < NSPLIT; i++) {
            cudaEventCreateWithFlags(&evG1[i], cudaEventDisableTiming);
            cudaEventCreateWithFlags(&evSM[i], cudaEventDisableTiming);
        }
        cudaEventCreateWithFlags(&evj, cudaEventDisableTiming);
        cudaFuncSetAttribute(gemm1_tc, cudaFuncAttributeMaxDynamicSharedMemorySize, SMEM_BYTES);
        cudaFuncSetAttribute(gemm2_tc, cudaFuncAttributeMaxDynamicSharedMemorySize, SMEM_BYTES);
    }

    // Preprocessing + all gemm1 slices on the origin stream (tensor stays hot)
    split_u<<<2048, 256>>>(Uw);
    fuse_x<<<dim3(LP / 32, D / 32, B), 256>>>(x);
    for (int i = 0; i < NSPLIT; i++) {
        gemm1_tc<<<dim3((L + 127) / 128, (Y + 127) / 128, BPS), 256, SMEM_BYTES>>>(i * BPS);
        cudaEventRecord(evG1[i], 0);
    }

    // Stream C: softmax per slice, gated on its gemm1
    for (int i = 0; i < NSPLIT; i++) {
        cudaStreamWaitEvent(sC, evG1[i], 0);
        softmax_rows<<<BPS * Y, 256, 0, sC>>>(out_alpha, i * BPS);
        cudaEventRecord(evSM[i], sC);
    }

    // Stream B: gemm2 per slice, gated on its softmax
    for (int i = 0; i < NSPLIT; i++) {
        cudaStreamWaitEvent(sB, evSM[i], 0);
        gemm2_tc<<<dim3(D / 128, (Y + 127) / 128, BPS), 256, SMEM_BYTES, sB>>>(out_m, fw, i * BPS);
    }

    final2<<<(B * Y + 255) / 256, 256, 0, sB>>>(fb, target, out_y);
    loss_reduce<<<1, 256, 0, sB>>>(out_loss);

    cudaEventRecord(evj, sB);
    cudaStreamWaitEvent(0, evj, 0);
}